// round 2
// baseline (speedup 1.0000x reference)
#include <cuda_runtime.h>
#include <math_constants.h>

#define THREADS 256
#define NWARPS  8

#define N_SENT_MAX (1 << 17)
#define BAGS_MAX   8192
#define D_MAX      690
#define C_MAX      53

// GEMM tiling
#define GB 32      // bags per CTA tile
#define GC 64      // classes per CTA tile (padded, only C valid)
#define DK 32      // d-chunk

// Scratch
__device__ float g_logit[N_SENT_MAX];
__device__ float g_aw[C_MAX * D_MAX];                    // att*rel, [C,D]
__device__ float g_repre[(size_t)BAGS_MAX * D_MAX];      // normalized bag reps

__global__ void precompute_aw_kernel(const float* __restrict__ rel,
                                     const float* __restrict__ att, int n2) {
    int i = blockIdx.x * blockDim.x + threadIdx.x;
    if (i < n2) {
        const float2 a = ((const float2*)att)[i];
        const float2 r = ((const float2*)rel)[i];
        ((float2*)g_aw)[i] = make_float2(a.x * r.x, a.y * r.y);
    }
}

__device__ __forceinline__ float warp_sum(float v) {
    #pragma unroll
    for (int o = 16; o; o >>= 1) v += __shfl_down_sync(0xffffffffu, v, o);
    return v;
}
__device__ __forceinline__ float warp_max(float v) {
    #pragma unroll
    for (int o = 16; o; o >>= 1) v = fmaxf(v, __shfl_down_sync(0xffffffffu, v, o));
    return v;
}

// ---------------------------------------------------------------------------
// Kernel 1: per-bag attention softmax + weighted bag representation
// ---------------------------------------------------------------------------
__global__ void __launch_bounds__(THREADS)
bag_kernel(const float* __restrict__ x,
           const int*   __restrict__ query,
           const int*   __restrict__ scope,
           int D)
{
    const int b     = blockIdx.x;
    const int start = scope[b];
    const int end   = scope[b + 1];
    const int cnt   = end - start;
    const int tid   = threadIdx.x;
    const int wid   = tid >> 5;
    const int lane  = tid & 31;
    const int D2    = D >> 1;          // 345 (D even)

    __shared__ float s_red[NWARPS];
    __shared__ float s_w[THREADS];

    // ---- Pass A: logit_i = dot(x_i, aw[q_i]), warp-per-row, float2 loads ----
    for (int i = start + wid; i < end; i += NWARPS) {
        const int q = query[i];
        const float2* __restrict__ xr = (const float2*)(x    + (size_t)i * D);
        const float2* __restrict__ ar = (const float2*)(g_aw + (size_t)q * D);
        float p = 0.f;
        for (int d = lane; d < D2; d += 32) {
            const float2 xv = xr[d];
            const float2 av = ar[d];
            p = fmaf(xv.x, av.x, p);
            p = fmaf(xv.y, av.y, p);
        }
        p = warp_sum(p);
        if (lane == 0) g_logit[i] = p;
    }
    __syncthreads();

    // ---- segment max ----
    float lm = -CUDART_INF_F;
    for (int i = start + tid; i < end; i += THREADS) lm = fmaxf(lm, g_logit[i]);
    lm = warp_max(lm);
    if (lane == 0) s_red[wid] = lm;
    __syncthreads();
    if (wid == 0) {
        float v = (lane < NWARPS) ? s_red[lane] : -CUDART_INF_F;
        v = warp_max(v);
        if (lane == 0) s_red[0] = v;
    }
    __syncthreads();
    const float m = s_red[0];
    __syncthreads();

    // ---- segment exp-sum ----
    float ls = 0.f;
    for (int i = start + tid; i < end; i += THREADS) {
        float e = expf(g_logit[i] - m);
        g_logit[i] = e;
        ls += e;
    }
    ls = warp_sum(ls);
    if (lane == 0) s_red[wid] = ls;
    __syncthreads();
    if (wid == 0) {
        float v = (lane < NWARPS) ? s_red[lane] : 0.f;
        v = warp_sum(v);
        if (lane == 0) s_red[0] = v;
    }
    __syncthreads();
    const float inv_denom = 1.f / s_red[0];

    // ---- Pass B: repre[d] = sum_i (w_i/denom) * x[i,d]; float2 columns ----
    float2 acc0 = make_float2(0.f, 0.f);
    float2 acc1 = make_float2(0.f, 0.f);
    const int d2a = tid;               // always < 345
    const int d2b = tid + THREADS;     // valid if < D2
    const bool hasB = (d2b < D2);

    for (int base = 0; base < cnt; base += THREADS) {
        __syncthreads();
        if (base + tid < cnt) s_w[tid] = g_logit[start + base + tid] * inv_denom;
        __syncthreads();
        const int lim = min(THREADS, cnt - base);
        for (int j = 0; j < lim; j++) {
            const float wg = s_w[j];
            const float2* __restrict__ xr =
                (const float2*)(x + (size_t)(start + base + j) * D);
            const float2 v0 = xr[d2a];
            acc0.x = fmaf(wg, v0.x, acc0.x);
            acc0.y = fmaf(wg, v0.y, acc0.y);
            if (hasB) {
                const float2 v1 = xr[d2b];
                acc1.x = fmaf(wg, v1.x, acc1.x);
                acc1.y = fmaf(wg, v1.y, acc1.y);
            }
        }
    }
    float2* __restrict__ rp = (float2*)(g_repre + (size_t)b * D);
    rp[d2a] = acc0;
    if (hasB) rp[d2b] = acc1;
}

// ---------------------------------------------------------------------------
// Kernel 2: out[B,C] = repre[B,D] @ rel_w[C,D]^T + bias
// CTA tile: GB=32 bags x GC=64 classes; thread = 2 bags x 4 classes
// ---------------------------------------------------------------------------
__global__ void __launch_bounds__(THREADS)
classify_kernel(const float* __restrict__ rel_w,
                const float* __restrict__ bias,
                float*       __restrict__ out,
                int D, int C, int B)
{
    __shared__ float s_rep[GB][DK + 1];
    __shared__ float s_rel[GC][DK + 1];

    const int tid = threadIdx.x;
    const int tx  = tid & 15;          // class group: classes tx*4 .. tx*4+3
    const int ty  = tid >> 4;          // bag group:   bags   ty*2 .. ty*2+1
    const int b0  = blockIdx.x * GB;

    float acc[2][4];
    #pragma unroll
    for (int i = 0; i < 2; i++)
        #pragma unroll
        for (int j = 0; j < 4; j++) acc[i][j] = 0.f;

    for (int d0 = 0; d0 < D; d0 += DK) {
        // load rel tile [GC x DK], zero-pad rows >= C and cols >= D
        for (int idx = tid; idx < GC * DK; idx += THREADS) {
            const int r = idx / DK;
            const int d = idx - r * DK;
            float v = 0.f;
            if (r < C && d0 + d < D) v = rel_w[(size_t)r * D + d0 + d];
            s_rel[r][d] = v;
        }
        // load rep tile [GB x DK]
        for (int idx = tid; idx < GB * DK; idx += THREADS) {
            const int r = idx / DK;
            const int d = idx - r * DK;
            float v = 0.f;
            if (b0 + r < B && d0 + d < D) v = g_repre[(size_t)(b0 + r) * D + d0 + d];
            s_rep[r][d] = v;
        }
        __syncthreads();

        #pragma unroll 8
        for (int dd = 0; dd < DK; dd++) {
            float rep[2], rel[4];
            #pragma unroll
            for (int i = 0; i < 2; i++) rep[i] = s_rep[ty * 2 + i][dd];
            #pragma unroll
            for (int j = 0; j < 4; j++) rel[j] = s_rel[tx * 4 + j][dd];
            #pragma unroll
            for (int i = 0; i < 2; i++)
                #pragma unroll
                for (int j = 0; j < 4; j++)
                    acc[i][j] = fmaf(rep[i], rel[j], acc[i][j]);
        }
        __syncthreads();
    }

    #pragma unroll
    for (int i = 0; i < 2; i++) {
        const int b = b0 + ty * 2 + i;
        if (b >= B) continue;
        #pragma unroll
        for (int j = 0; j < 4; j++) {
            const int c = tx * 4 + j;
            if (c < C) out[(size_t)b * C + c] = acc[i][j] + bias[c];
        }
    }
}

extern "C" void kernel_launch(void* const* d_in, const int* in_sizes, int n_in,
                              void* d_out, int out_size)
{
    const float* x     = (const float*)d_in[0];
    const float* rel_w = (const float*)d_in[1];
    const float* att_w = (const float*)d_in[2];
    const float* bias  = (const float*)d_in[3];
    const int*   query = (const int*)  d_in[4];
    const int*   scope = (const int*)  d_in[5];

    const int C = in_sizes[3];           // 53
    const int D = in_sizes[1] / C;       // 690
    const int B = in_sizes[5] - 1;       // 8192

    const int naw2 = (C * D) / 2;
    precompute_aw_kernel<<<(naw2 + 255) / 256, 256>>>(rel_w, att_w, naw2);
    bag_kernel<<<B, THREADS>>>(x, query, scope, D);
    classify_kernel<<<(B + GB - 1) / GB, THREADS>>>(rel_w, bias, (float*)d_out, D, C, B);
}

// round 3
// speedup vs baseline: 1.0343x; 1.0343x over previous
#include <cuda_runtime.h>
#include <math_constants.h>

#define THREADS 256
#define NWARPS  8
#define RB      4            // sentences per block-reduce batch

#define BAGS_MAX 8192
#define D_MAX    690
#define C_MAX    53

// GEMM tiling for classifier
#define GB 32
#define GC 64
#define DK 32

__device__ float g_aw[C_MAX * D_MAX];                    // att*rel, [C,D]
__device__ float g_repre[(size_t)BAGS_MAX * D_MAX];      // normalized bag reps

__global__ void precompute_aw_kernel(const float* __restrict__ rel,
                                     const float* __restrict__ att, int n2) {
    int i = blockIdx.x * blockDim.x + threadIdx.x;
    if (i < n2) {
        const float2 a = ((const float2*)att)[i];
        const float2 r = ((const float2*)rel)[i];
        ((float2*)g_aw)[i] = make_float2(a.x * r.x, a.y * r.y);
    }
}

// ---------------------------------------------------------------------------
// Kernel 1: fused one-pass online-softmax bag representation.
// One CTA per bag. Threads own float2 columns da=tid, db=tid+256 (db partial).
// x is read from global exactly once, kept in registers between the logit
// computation and the weighted accumulation.
// ---------------------------------------------------------------------------
__global__ void __launch_bounds__(THREADS)
bag_kernel(const float* __restrict__ x,
           const int*   __restrict__ query,
           const int*   __restrict__ scope,
           int D)
{
    const int b     = blockIdx.x;
    const int start = scope[b];
    const int end   = scope[b + 1];
    const int tid   = threadIdx.x;
    const int wid   = tid >> 5;
    const int lane  = tid & 31;
    const int D2    = D >> 1;            // 345
    const int da    = tid;               // float2 index, always < 345
    const int db    = tid + THREADS;     // valid if < D2 (tid < 89)
    const bool hb   = (db < D2);

    __shared__ float4 s_part[NWARPS];

    float2 r0 = make_float2(0.f, 0.f);
    float2 r1 = make_float2(0.f, 0.f);
    float  m  = -CUDART_INF_F;
    float  Z  = 0.f;

    for (int base = start; base < end; base += RB) {
        // ---- load RB sentences' x and aw slices (big MLP batch) ----
        float2 xa[RB], xb[RB];
        float  part[RB];
        #pragma unroll
        for (int j = 0; j < RB; j++) {
            const int  i  = base + j;
            const bool v  = (i < end);
            const int  ii = v ? i : start;              // safe address
            const int  q  = query[ii];
            const float2* __restrict__ xr = (const float2*)(x    + (size_t)ii * D);
            const float2* __restrict__ ar = (const float2*)(g_aw + (size_t)q  * D);
            float2 x0 = xr[da];
            float2 a0 = ar[da];
            float2 x1 = make_float2(0.f, 0.f), a1 = make_float2(0.f, 0.f);
            if (hb) { x1 = xr[db]; a1 = ar[db]; }
            if (!v) { x0 = make_float2(0.f, 0.f); a0 = make_float2(0.f, 0.f); }
            xa[j] = x0; xb[j] = x1;
            float p = x0.x * a0.x;
            p = fmaf(x0.y, a0.y, p);
            p = fmaf(x1.x, a1.x, p);
            p = fmaf(x1.y, a1.y, p);
            part[j] = p;
        }

        // ---- block reduce 4 logits ----
        #pragma unroll
        for (int j = 0; j < RB; j++)
            #pragma unroll
            for (int o = 16; o; o >>= 1)
                part[j] += __shfl_down_sync(0xffffffffu, part[j], o);

        __syncthreads();   // protect s_part from previous iteration's readers
        if (lane == 0)
            s_part[wid] = make_float4(part[0], part[1], part[2], part[3]);
        __syncthreads();

        float l0 = 0.f, l1 = 0.f, l2 = 0.f, l3 = 0.f;
        #pragma unroll
        for (int w = 0; w < NWARPS; w++) {
            const float4 p = s_part[w];
            l0 += p.x; l1 += p.y; l2 += p.z; l3 += p.w;
        }
        const int nv = end - base;      // valid rows this batch (>=1)
        if (nv < 2) l1 = -CUDART_INF_F;
        if (nv < 3) l2 = -CUDART_INF_F;
        if (nv < 4) l3 = -CUDART_INF_F;

        // ---- online softmax update ----
        float m_new = fmaxf(fmaxf(fmaxf(fmaxf(m, l0), l1), l2), l3);
        const float alpha = __expf(m - m_new);
        float e[RB];
        e[0] = __expf(l0 - m_new);
        e[1] = __expf(l1 - m_new);
        e[2] = __expf(l2 - m_new);
        e[3] = __expf(l3 - m_new);
        Z = Z * alpha + ((e[0] + e[1]) + (e[2] + e[3]));
        r0.x *= alpha; r0.y *= alpha; r1.x *= alpha; r1.y *= alpha;
        #pragma unroll
        for (int j = 0; j < RB; j++) {
            r0.x = fmaf(e[j], xa[j].x, r0.x);
            r0.y = fmaf(e[j], xa[j].y, r0.y);
            r1.x = fmaf(e[j], xb[j].x, r1.x);
            r1.y = fmaf(e[j], xb[j].y, r1.y);
        }
        m = m_new;
    }

    const float inv = 1.f / Z;
    float2* __restrict__ rp = (float2*)(g_repre + (size_t)b * D);
    rp[da] = make_float2(r0.x * inv, r0.y * inv);
    if (hb) rp[db] = make_float2(r1.x * inv, r1.y * inv);
}

// ---------------------------------------------------------------------------
// Kernel 2: out[B,C] = repre[B,D] @ rel_w[C,D]^T + bias
// ---------------------------------------------------------------------------
__global__ void __launch_bounds__(THREADS)
classify_kernel(const float* __restrict__ rel_w,
                const float* __restrict__ bias,
                float*       __restrict__ out,
                int D, int C, int B)
{
    __shared__ float s_rep[GB * (DK + 1)];
    __shared__ float s_rel[GC * (DK + 1)];

    const int tid = threadIdx.x;
    const int tx  = tid & 15;          // classes tx*4 .. tx*4+3
    const int ty  = tid >> 4;          // bags    ty*2 .. ty*2+1
    const int b0  = blockIdx.x * GB;

    float acc[2][4];
    #pragma unroll
    for (int i = 0; i < 2; i++)
        #pragma unroll
        for (int j = 0; j < 4; j++) acc[i][j] = 0.f;

    for (int d0 = 0; d0 < D; d0 += DK) {
        // rel tile [GC x DK] via float2 (D even, d0 even -> pairs valid together)
        for (int idx = tid; idx < GC * (DK / 2); idx += THREADS) {
            const int r  = idx >> 4;           // /16
            const int dc = (idx & 15) << 1;    // 0,2,..,30
            float2 v = make_float2(0.f, 0.f);
            if (r < C && d0 + dc < D)
                v = *(const float2*)(rel_w + (size_t)r * D + d0 + dc);
            s_rel[r * (DK + 1) + dc]     = v.x;
            s_rel[r * (DK + 1) + dc + 1] = v.y;
        }
        // rep tile [GB x DK]
        for (int idx = tid; idx < GB * (DK / 2); idx += THREADS) {
            const int r  = idx >> 4;
            const int dc = (idx & 15) << 1;
            float2 v = make_float2(0.f, 0.f);
            if (d0 + dc < D)
                v = *(const float2*)(g_repre + (size_t)(b0 + r) * D + d0 + dc);
            s_rep[r * (DK + 1) + dc]     = v.x;
            s_rep[r * (DK + 1) + dc + 1] = v.y;
        }
        __syncthreads();

        #pragma unroll 8
        for (int dd = 0; dd < DK; dd++) {
            float rep[2], rel[4];
            #pragma unroll
            for (int i = 0; i < 2; i++) rep[i] = s_rep[(ty * 2 + i) * (DK + 1) + dd];
            #pragma unroll
            for (int j = 0; j < 4; j++) rel[j] = s_rel[(tx * 4 + j) * (DK + 1) + dd];
            #pragma unroll
            for (int i = 0; i < 2; i++)
                #pragma unroll
                for (int j = 0; j < 4; j++)
                    acc[i][j] = fmaf(rep[i], rel[j], acc[i][j]);
        }
        __syncthreads();
    }

    #pragma unroll
    for (int i = 0; i < 2; i++) {
        const int b = b0 + ty * 2 + i;
        if (b >= B) continue;
        #pragma unroll
        for (int j = 0; j < 4; j++) {
            const int c = tx * 4 + j;
            if (c < C) out[(size_t)b * C + c] = acc[i][j] + bias[c];
        }
    }
}

extern "C" void kernel_launch(void* const* d_in, const int* in_sizes, int n_in,
                              void* d_out, int out_size)
{
    const float* x     = (const float*)d_in[0];
    const float* rel_w = (const float*)d_in[1];
    const float* att_w = (const float*)d_in[2];
    const float* bias  = (const float*)d_in[3];
    const int*   query = (const int*)  d_in[4];
    const int*   scope = (const int*)  d_in[5];

    const int C = in_sizes[3];           // 53
    const int D = in_sizes[1] / C;       // 690
    const int B = in_sizes[5] - 1;       // 8192

    const int naw2 = (C * D) / 2;
    precompute_aw_kernel<<<(naw2 + 255) / 256, 256>>>(rel_w, att_w, naw2);
    bag_kernel<<<B, THREADS>>>(x, query, scope, D);
    classify_kernel<<<(B + GB - 1) / GB, THREADS>>>(rel_w, bias, (float*)d_out, D, C, B);
}